// round 1
// baseline (speedup 1.0000x reference)
#include <cuda_runtime.h>
#include <math.h>

#define N_EMBD   2048
#define N_HEAD   32
#define N_GROUPS 8
#define HEAD_DIM 64
#define Q_PER_KV 4
#define QKV_DIM  3072          // (4+2)*8*64
#define BATCH    2
#define SEQ      2048
#define M_TOT    (BATCH*SEQ)   // 4096

// ---------------- scratch (device globals: no allocations allowed) ----------
__device__ float g_qkv[(size_t)BATCH*SEQ*QKV_DIM];               // 50.3 MB
__device__ float g_q  [(size_t)BATCH*N_HEAD*SEQ*HEAD_DIM];       // 33.5 MB
__device__ float g_k  [(size_t)BATCH*N_GROUPS*SEQ*HEAD_DIM];     //  8.4 MB
__device__ float g_v  [(size_t)BATCH*N_GROUPS*SEQ*HEAD_DIM];     //  8.4 MB
__device__ float g_ao [(size_t)BATCH*SEQ*N_EMBD];                // 33.5 MB

// ---------------- GEMM: C[m,n] = sum_k A[m,k] * W[n,k]  (both K-contiguous) -
// Tiles: BM=BN=128, BK=8, 256 threads, 8x8 per-thread micro-tile.
__global__ __launch_bounds__(256) void sgemm_nt(
    const float* __restrict__ A, const float* __restrict__ W,
    float* __restrict__ C, int M, int N, int K)
{
    __shared__ float As[8][128];
    __shared__ float Bs[8][128];

    const int tid = threadIdx.x;
    const int bm = blockIdx.y, bn = blockIdx.x;
    const int lr = tid >> 1;            // 0..127 : tile row to load
    const int lc = (tid & 1) * 4;       // 0 or 4 : k-offset (float4)
    const int tx = tid & 15;            // micro-tile col group
    const int ty = tid >> 4;            // micro-tile row group

    const float* Ab = A + (size_t)(bm * 128) * K;
    const float* Wb = W + (size_t)(bn * 128) * K;

    float acc[8][8];
#pragma unroll
    for (int i = 0; i < 8; i++)
#pragma unroll
        for (int j = 0; j < 8; j++) acc[i][j] = 0.f;

    for (int k0 = 0; k0 < K; k0 += 8) {
        float4 av = *(const float4*)(Ab + (size_t)lr * K + k0 + lc);
        float4 wv = *(const float4*)(Wb + (size_t)lr * K + k0 + lc);

        __syncthreads();   // previous compute must be done before overwrite
        As[lc + 0][lr] = av.x; As[lc + 1][lr] = av.y;
        As[lc + 2][lr] = av.z; As[lc + 3][lr] = av.w;
        Bs[lc + 0][lr] = wv.x; Bs[lc + 1][lr] = wv.y;
        Bs[lc + 2][lr] = wv.z; Bs[lc + 3][lr] = wv.w;
        __syncthreads();

#pragma unroll
        for (int kk = 0; kk < 8; kk++) {
            float a[8], b[8];
            *(float4*)&a[0] = *(const float4*)&As[kk][ty * 8];
            *(float4*)&a[4] = *(const float4*)&As[kk][ty * 8 + 4];
            *(float4*)&b[0] = *(const float4*)&Bs[kk][tx * 8];
            *(float4*)&b[4] = *(const float4*)&Bs[kk][tx * 8 + 4];
#pragma unroll
            for (int i = 0; i < 8; i++)
#pragma unroll
                for (int j = 0; j < 8; j++)
                    acc[i][j] = fmaf(a[i], b[j], acc[i][j]);
        }
    }

#pragma unroll
    for (int i = 0; i < 8; i++) {
        size_t base = (size_t)(bm * 128 + ty * 8 + i) * N + bn * 128 + tx * 8;
        *(float4*)&C[base]     = *(float4*)&acc[i][0];
        *(float4*)&C[base + 4] = *(float4*)&acc[i][4];
    }
}

// ---------------- RoPE + split qkv -> q[B,H,T,D], k[B,G,T,D], v[B,G,T,D] ----
__global__ __launch_bounds__(256) void rope_split(
    const float* __restrict__ qkv,
    const float* __restrict__ cosT, const float* __restrict__ sinT)
{
    const int bt = blockIdx.x;          // 0..B*T-1
    const int b = bt / SEQ, t = bt % SEQ;
    const float* row = qkv + (size_t)bt * QKV_DIM;

    __shared__ float cs[32], sn[32];
    if (threadIdx.x < 32) {
        cs[threadIdx.x] = cosT[t * 32 + threadIdx.x];
        sn[threadIdx.x] = sinT[t * 32 + threadIdx.x];
    }
    __syncthreads();

    // Q: 32 heads x 32 half-pairs = 1024 items
    for (int it = threadIdx.x; it < 1024; it += 256) {
        int h = it >> 5, j = it & 31;
        int g = h >> 2, slot = h & 3;
        const float* src = row + (g * 6 + slot) * 64;
        float x1 = src[j], x2 = src[j + 32];
        float c = cs[j], s = sn[j];
        float* dst = g_q + ((size_t)(b * N_HEAD + h) * SEQ + t) * 64;
        dst[j]      = x1 * c - x2 * s;
        dst[j + 32] = x2 * c + x1 * s;
    }
    // K: 8 groups x 32 half-pairs = 256 items (one per thread)
    {
        int it = threadIdx.x;
        int g = it >> 5, j = it & 31;
        const float* src = row + (g * 6 + 4) * 64;
        float x1 = src[j], x2 = src[j + 32];
        float c = cs[j], s = sn[j];
        float* dst = g_k + ((size_t)(b * N_GROUPS + g) * SEQ + t) * 64;
        dst[j]      = x1 * c - x2 * s;
        dst[j + 32] = x2 * c + x1 * s;
    }
    // V: plain copy, 8 groups x 64 dims = 512 items
    for (int it = threadIdx.x; it < 512; it += 256) {
        int g = it >> 6, d = it & 63;
        g_v[((size_t)(b * N_GROUPS + g) * SEQ + t) * 64 + d] = row[(g * 6 + 5) * 64 + d];
    }
}

// ---------------- Flash attention (fp32): BLOCK_Q=64, KV tile = 32 ---------
// 8 warps, each owns 8 query rows. Per lane: 1 key for QK^T, 2 dims for P.V.
__global__ __launch_bounds__(256) void attn_kernel()
{
    __shared__ float Qs[64][64];
    __shared__ float Ks[32][68];   // stride 68: float4-aligned, bounded conflicts
    __shared__ float Vs[32][64];

    const int tid  = threadIdx.x;
    const int warp = tid >> 5, lane = tid & 31;
    const int qt = blockIdx.x;           // 0..31 query tile
    const int bh = blockIdx.y;           // 0..63
    const int b = bh >> 5, h = bh & 31, g = h >> 2;

    const float* Qg = g_q + ((size_t)(b * N_HEAD + h) * SEQ + qt * 64) * 64;
    const float* Kg = g_k + (size_t)(b * N_GROUPS + g) * SEQ * 64;
    const float* Vg = g_v + (size_t)(b * N_GROUPS + g) * SEQ * 64;

    // load Q tile (64x64): 1024 float4s
    for (int i = tid; i < 64 * 16; i += 256) {
        int r = i >> 4, c4 = (i & 15) << 2;
        *(float4*)&Qs[r][c4] = *(const float4*)(Qg + r * 64 + c4);
    }

    const int r0 = warp * 8;
    float m[8], l[8], o0[8], o1[8];
#pragma unroll
    for (int r = 0; r < 8; r++) { m[r] = -1e30f; l[r] = 0.f; o0[r] = 0.f; o1[r] = 0.f; }

    const float scale = 0.125f;  // 1/sqrt(64)

    for (int kt = 0; kt < SEQ / 32; kt++) {
        __syncthreads();   // previous compute done (also publishes Q on iter 0)
        // load K,V tiles (32x64 each): 512 float4s, 2 per thread
        for (int i = tid; i < 512; i += 256) {
            int r = i >> 4, c4 = (i & 15) << 2;
            float4 k4 = *(const float4*)(Kg + ((size_t)(kt * 32 + r)) * 64 + c4);
            Ks[r][c4] = k4.x; Ks[r][c4 + 1] = k4.y; Ks[r][c4 + 2] = k4.z; Ks[r][c4 + 3] = k4.w;
            *(float4*)&Vs[r][c4] = *(const float4*)(Vg + ((size_t)(kt * 32 + r)) * 64 + c4);
        }
        __syncthreads();

        // scores: this lane's key = kt*32 + lane, 8 rows
        float s[8];
#pragma unroll
        for (int r = 0; r < 8; r++) s[r] = 0.f;
#pragma unroll
        for (int d4 = 0; d4 < 64; d4 += 4) {
            float4 kv = *(const float4*)&Ks[lane][d4];
#pragma unroll
            for (int r = 0; r < 8; r++) {
                float4 qv = *(const float4*)&Qs[r0 + r][d4];
                s[r] += qv.x * kv.x + qv.y * kv.y + qv.z * kv.z + qv.w * kv.w;
            }
        }

        // online softmax update per row
        float p[8];
#pragma unroll
        for (int r = 0; r < 8; r++) {
            float sr = s[r] * scale;
            float mt = sr;
#pragma unroll
            for (int off = 16; off > 0; off >>= 1)
                mt = fmaxf(mt, __shfl_xor_sync(0xffffffffu, mt, off));
            float mn = fmaxf(m[r], mt);
            float pe = __expf(sr - mn);
            float alpha = __expf(m[r] - mn);
            float ps = pe;
#pragma unroll
            for (int off = 16; off > 0; off >>= 1)
                ps += __shfl_xor_sync(0xffffffffu, ps, off);
            l[r] = l[r] * alpha + ps;
            m[r] = mn;
            o0[r] *= alpha; o1[r] *= alpha;
            p[r] = pe;
        }

        // P.V : lane owns dims (2*lane, 2*lane+1)
#pragma unroll
        for (int kk = 0; kk < 32; kk++) {
            float2 v2 = *(const float2*)&Vs[kk][lane * 2];
#pragma unroll
            for (int r = 0; r < 8; r++) {
                float pv = __shfl_sync(0xffffffffu, p[r], kk);
                o0[r] = fmaf(pv, v2.x, o0[r]);
                o1[r] = fmaf(pv, v2.y, o1[r]);
            }
        }
    }

    // write out: g_ao[b][t][h*64 + d]
#pragma unroll
    for (int r = 0; r < 8; r++) {
        int t = qt * 64 + r0 + r;
        float inv = 1.f / l[r];
        float2 res; res.x = o0[r] * inv; res.y = o1[r] * inv;
        *(float2*)&g_ao[((size_t)(b * SEQ + t)) * N_EMBD + h * 64 + lane * 2] = res;
    }
}

// ---------------------------------------------------------------------------
extern "C" void kernel_launch(void* const* d_in, const int* in_sizes, int n_in,
                              void* d_out, int out_size)
{
    const float* x      = (const float*)d_in[0];
    const float* cosp   = (const float*)d_in[1];
    const float* sinp   = (const float*)d_in[2];
    const float* attn_w = (const float*)d_in[3];
    const float* proj_w = (const float*)d_in[4];
    float* out = (float*)d_out;

    float *qkv, *ao;
    cudaGetSymbolAddress((void**)&qkv, g_qkv);
    cudaGetSymbolAddress((void**)&ao,  g_ao);

    // 1) QKV projection: [4096,2048] x [3072,2048]^T
    sgemm_nt<<<dim3(QKV_DIM / 128, M_TOT / 128), 256>>>(x, attn_w, qkv,
                                                        M_TOT, QKV_DIM, N_EMBD);
    // 2) RoPE + head split
    rope_split<<<BATCH * SEQ, 256>>>(qkv, cosp, sinp);
    // 3) flash attention
    attn_kernel<<<dim3(SEQ / 64, BATCH * N_HEAD), 256>>>();
    // 4) output projection: [4096,2048] x [2048,2048]^T
    sgemm_nt<<<dim3(N_EMBD / 128, M_TOT / 128), 256>>>(ao, proj_w, out,
                                                       M_TOT, N_EMBD, N_EMBD);
}

// round 5
// speedup vs baseline: 1.3520x; 1.3520x over previous
#include <cuda_runtime.h>
#include <cuda_bf16.h>
#include <cstdint>
#include <math.h>

#define N_EMBD   2048
#define N_HEAD   32
#define N_GROUPS 8
#define HEAD_DIM 64
#define Q_PER_KV 4
#define QKV_DIM  3072
#define BATCH    2
#define SEQ      2048
#define M_TOT    (BATCH*SEQ)   // 4096

// ---------------- scratch (device globals; no allocations allowed) ---------
__device__ float g_qkv[(size_t)M_TOT*QKV_DIM];
__device__ float g_q  [(size_t)BATCH*N_HEAD*SEQ*HEAD_DIM];
__device__ float g_k  [(size_t)BATCH*N_GROUPS*SEQ*HEAD_DIM];
__device__ float g_v  [(size_t)BATCH*N_GROUPS*SEQ*HEAD_DIM];

__device__ __align__(128) __nv_bfloat16 g_xs_hi[(size_t)M_TOT*N_EMBD];
__device__ __align__(128) __nv_bfloat16 g_xs_lo[(size_t)M_TOT*N_EMBD];
__device__ __align__(128) __nv_bfloat16 g_aw_hi[(size_t)QKV_DIM*N_EMBD];
__device__ __align__(128) __nv_bfloat16 g_aw_lo[(size_t)QKV_DIM*N_EMBD];
__device__ __align__(128) __nv_bfloat16 g_pw_hi[(size_t)N_EMBD*N_EMBD];
__device__ __align__(128) __nv_bfloat16 g_pw_lo[(size_t)N_EMBD*N_EMBD];
__device__ __align__(128) __nv_bfloat16 g_ao_hi[(size_t)M_TOT*N_EMBD];
__device__ __align__(128) __nv_bfloat16 g_ao_lo[(size_t)M_TOT*N_EMBD];

// ====================== helpers (sm_80-compatible PTX only) ================
static __device__ __forceinline__ uint32_t smem_u32(const void* p) {
    uint32_t a;
    asm("{ .reg .u64 t; cvta.to.shared.u64 t, %1; cvt.u32.u64 %0, t; }"
        : "=r"(a) : "l"(p));
    return a;
}

#define CP16(dst, src) \
    asm volatile("cp.async.cg.shared.global [%0], [%1], 16;" :: "r"(dst), "l"(src))
#define CPCOMMIT() asm volatile("cp.async.commit_group;")
#define CPWAIT1()  asm volatile("cp.async.wait_group 1;" ::: "memory")
#define CPWAIT0()  asm volatile("cp.async.wait_group 0;" ::: "memory")

#define LDSM4(r0, r1, r2, r3, addr) \
    asm volatile("ldmatrix.sync.aligned.m8n8.x4.shared.b16 {%0,%1,%2,%3}, [%4];" \
        : "=r"(r0), "=r"(r1), "=r"(r2), "=r"(r3) : "r"(addr))

#define MMA_BF16(c, a, b0, b1) \
    asm volatile("mma.sync.aligned.m16n8k16.row.col.f32.bf16.bf16.f32 " \
        "{%0,%1,%2,%3}, {%4,%5,%6,%7}, {%8,%9}, {%0,%1,%2,%3};" \
        : "+f"((c)[0]), "+f"((c)[1]), "+f"((c)[2]), "+f"((c)[3]) \
        : "r"((a)[0]), "r"((a)[1]), "r"((a)[2]), "r"((a)[3]), "r"(b0), "r"(b1))

// ================ fp32 -> bf16 hi/lo split (prepass) =======================
__global__ __launch_bounds__(256) void split_kernel(
    const float4* __restrict__ in, uint2* __restrict__ hi, uint2* __restrict__ lo, int n4)
{
    for (int i = blockIdx.x * blockDim.x + threadIdx.x; i < n4;
         i += gridDim.x * blockDim.x) {
        float4 v = in[i];
        __nv_bfloat16 h0 = __float2bfloat16(v.x);
        __nv_bfloat16 h1 = __float2bfloat16(v.y);
        __nv_bfloat16 h2 = __float2bfloat16(v.z);
        __nv_bfloat16 h3 = __float2bfloat16(v.w);
        __nv_bfloat16 l0 = __float2bfloat16(v.x - __bfloat162float(h0));
        __nv_bfloat16 l1 = __float2bfloat16(v.y - __bfloat162float(h1));
        __nv_bfloat16 l2 = __float2bfloat16(v.z - __bfloat162float(h2));
        __nv_bfloat16 l3 = __float2bfloat16(v.w - __bfloat162float(h3));
        uint2 H, L;
        H.x = (uint32_t)__bfloat16_as_ushort(h0) | ((uint32_t)__bfloat16_as_ushort(h1) << 16);
        H.y = (uint32_t)__bfloat16_as_ushort(h2) | ((uint32_t)__bfloat16_as_ushort(h3) << 16);
        L.x = (uint32_t)__bfloat16_as_ushort(l0) | ((uint32_t)__bfloat16_as_ushort(l1) << 16);
        L.y = (uint32_t)__bfloat16_as_ushort(l2) | ((uint32_t)__bfloat16_as_ushort(l3) << 16);
        hi[i] = H; lo[i] = L;
    }
}

// ============ mma.sync GEMM: C = A @ B^T (3-term bf16 split) ===============
// CTA 128x128, BK=32, 256 threads (8 warps, 2x4). Rows padded to 40 elems
// (80B) so ldmatrix row addresses land on distinct bank groups.
#define ROWB 80           // bytes per smem row (40 bf16)
#define TILE_B (128*ROWB) // 10240 bytes per operand tile
#define STAGE_B (4*TILE_B)

__device__ __forceinline__ void g_load_stage(
    const __nv_bfloat16* pAh, const __nv_bfloat16* pAl,
    const __nv_bfloat16* pBh, const __nv_bfloat16* pBl,
    int K, int k0, uint32_t base, int tid)
{
    const __nv_bfloat16* srcs[4] = { pAh, pAl, pBh, pBl };
#pragma unroll
    for (int t = 0; t < 4; t++) {
#pragma unroll
        for (int j = 0; j < 2; j++) {
            const int idx = (tid << 1) | j;       // 0..511
            const int row = idx >> 2, ch = idx & 3;
            const char* gsrc = (const char*)(srcs[t] + (size_t)row * K + k0) + ch * 16;
            uint32_t dst = base + t * TILE_B + row * ROWB + ch * 16;
            CP16(dst, gsrc);
        }
    }
    CPCOMMIT();
}

__global__ __launch_bounds__(256, 1) void gemm_mma(
    const __nv_bfloat16* __restrict__ Ah, const __nv_bfloat16* __restrict__ Al,
    const __nv_bfloat16* __restrict__ Bh, const __nv_bfloat16* __restrict__ Bl,
    float* __restrict__ C, int M, int N, int K)
{
    extern __shared__ char dynsmem[];
    const uint32_t tiles = smem_u32(dynsmem);

    const int tid = threadIdx.x, warp = tid >> 5, lane = tid & 31;
    const int bm = blockIdx.y, bn = blockIdx.x;
    const int wm = warp & 1, wn = warp >> 1;     // 2 x 4 warp grid
    const int KC = K >> 5;                       // BK = 32

    const __nv_bfloat16* pAh = Ah + (size_t)(bm * 128) * K;
    const __nv_bfloat16* pAl = Al + (size_t)(bm * 128) * K;
    const __nv_bfloat16* pBh = Bh + (size_t)(bn * 128) * K;
    const __nv_bfloat16* pBl = Bl + (size_t)(bn * 128) * K;

    float acc[4][4][4];
#pragma unroll
    for (int i = 0; i < 4; i++)
#pragma unroll
        for (int j = 0; j < 4; j++)
#pragma unroll
            for (int q = 0; q < 4; q++) acc[i][j][q] = 0.f;

    g_load_stage(pAh, pAl, pBh, pBl, K, 0,  tiles,           tid);
    g_load_stage(pAh, pAl, pBh, pBl, K, 32, tiles + STAGE_B, tid);

    // ldmatrix per-lane address components
    const int a_row = wm * 64 + (lane & 15);
    const int a_ko  = (lane >> 4) * 16;                       // k half (bytes)
    const int b_row = wn * 32 + ((lane >> 4) << 3) + (lane & 7);
    const int b_ko  = ((lane >> 3) & 1) * 16;

    for (int kc = 0; kc < KC; kc++) {
        const int s = kc & 1;
        if (kc + 1 < KC) { CPWAIT1(); } else { CPWAIT0(); }
        __syncthreads();

        const uint32_t sAh = tiles + s * STAGE_B;
        const uint32_t sAl = sAh + TILE_B;
        const uint32_t sBh = sAh + 2 * TILE_B;
        const uint32_t sBl = sAh + 3 * TILE_B;

#pragma unroll
        for (int ks = 0; ks < 2; ks++) {
            const int kb = ks * 32;  // byte offset of k-step within row
            uint32_t ah[4][4], al[4][4], bh[2][4], bl[2][4];
#pragma unroll
            for (int mf = 0; mf < 4; mf++) {
                uint32_t ad = sAh + (a_row + mf * 16) * ROWB + a_ko + kb;
                LDSM4(ah[mf][0], ah[mf][1], ah[mf][2], ah[mf][3], ad);
            }
#pragma unroll
            for (int np = 0; np < 2; np++) {
                uint32_t bd = sBh + (b_row + np * 16) * ROWB + b_ko + kb;
                LDSM4(bh[np][0], bh[np][1], bh[np][2], bh[np][3], bd);
            }
#pragma unroll
            for (int mf = 0; mf < 4; mf++)
#pragma unroll
                for (int nf = 0; nf < 4; nf++)
                    MMA_BF16(acc[mf][nf], ah[mf],
                             bh[nf >> 1][(nf & 1) * 2], bh[nf >> 1][(nf & 1) * 2 + 1]);
#pragma unroll
            for (int np = 0; np < 2; np++) {
                uint32_t bd = sBl + (b_row + np * 16) * ROWB + b_ko + kb;
                LDSM4(bl[np][0], bl[np][1], bl[np][2], bl[np][3], bd);
            }
#pragma unroll
            for (int mf = 0; mf < 4; mf++)
#pragma unroll
                for (int nf = 0; nf < 4; nf++)
                    MMA_BF16(acc[mf][nf], ah[mf],
                             bl[nf >> 1][(nf & 1) * 2], bl[nf >> 1][(nf & 1) * 2 + 1]);
#pragma unroll
            for (int mf = 0; mf < 4; mf++) {
                uint32_t ad = sAl + (a_row + mf * 16) * ROWB + a_ko + kb;
                LDSM4(al[mf][0], al[mf][1], al[mf][2], al[mf][3], ad);
            }
#pragma unroll
            for (int mf = 0; mf < 4; mf++)
#pragma unroll
                for (int nf = 0; nf < 4; nf++)
                    MMA_BF16(acc[mf][nf], al[mf],
                             bh[nf >> 1][(nf & 1) * 2], bh[nf >> 1][(nf & 1) * 2 + 1]);
        }
        __syncthreads();   // stage s fully consumed before refill
        if (kc + 2 < KC)
            g_load_stage(pAh, pAl, pBh, pBl, K, (kc + 2) << 5, tiles + s * STAGE_B, tid);
    }

    // epilogue
    const int g = lane >> 2, tig = lane & 3;
#pragma unroll
    for (int mf = 0; mf < 4; mf++) {
#pragma unroll
        for (int nf = 0; nf < 4; nf++) {
            const int row = bm * 128 + wm * 64 + mf * 16 + g;
            const int col = bn * 128 + wn * 32 + nf * 8 + tig * 2;
            float2 r0; r0.x = acc[mf][nf][0]; r0.y = acc[mf][nf][1];
            float2 r1; r1.x = acc[mf][nf][2]; r1.y = acc[mf][nf][3];
            *(float2*)&C[(size_t)row * N + col]       = r0;
            *(float2*)&C[(size_t)(row + 8) * N + col] = r1;
        }
    }
}

// ---------------- RoPE + split qkv -> q[B,H,T,D], k[B,G,T,D], v[B,G,T,D] ----
__global__ __launch_bounds__(256) void rope_split(
    const float* __restrict__ qkv,
    const float* __restrict__ cosT, const float* __restrict__ sinT)
{
    const int bt = blockIdx.x;
    const int b = bt / SEQ, t = bt % SEQ;
    const float* row = qkv + (size_t)bt * QKV_DIM;

    __shared__ float cs[32], sn[32];
    if (threadIdx.x < 32) {
        cs[threadIdx.x] = cosT[t * 32 + threadIdx.x];
        sn[threadIdx.x] = sinT[t * 32 + threadIdx.x];
    }
    __syncthreads();

    for (int it = threadIdx.x; it < 1024; it += 256) {
        int h = it >> 5, j = it & 31;
        int g = h >> 2, slot = h & 3;
        const float* src = row + (g * 6 + slot) * 64;
        float x1 = src[j], x2 = src[j + 32];
        float c = cs[j], s = sn[j];
        float* dst = g_q + ((size_t)(b * N_HEAD + h) * SEQ + t) * 64;
        dst[j]      = x1 * c - x2 * s;
        dst[j + 32] = x2 * c + x1 * s;
    }
    {
        int it = threadIdx.x;
        int g = it >> 5, j = it & 31;
        const float* src = row + (g * 6 + 4) * 64;
        float x1 = src[j], x2 = src[j + 32];
        float c = cs[j], s = sn[j];
        float* dst = g_k + ((size_t)(b * N_GROUPS + g) * SEQ + t) * 64;
        dst[j]      = x1 * c - x2 * s;
        dst[j + 32] = x2 * c + x1 * s;
    }
    for (int it = threadIdx.x; it < 512; it += 256) {
        int g = it >> 6, d = it & 63;
        g_v[((size_t)(b * N_GROUPS + g) * SEQ + t) * 64 + d] = row[(g * 6 + 5) * 64 + d];
    }
}

// ---------------- Flash attention (fp32), writes split bf16 output ---------
__global__ __launch_bounds__(256) void attn_kernel()
{
    __shared__ float Qs[64][64];
    __shared__ float Ks[32][68];
    __shared__ float Vs[32][64];

    const int tid  = threadIdx.x;
    const int warp = tid >> 5, lane = tid & 31;
    const int qt = blockIdx.x;
    const int bh = blockIdx.y;
    const int b = bh >> 5, h = bh & 31, g = h >> 2;

    const float* Qg = g_q + ((size_t)(b * N_HEAD + h) * SEQ + qt * 64) * 64;
    const float* Kg = g_k + (size_t)(b * N_GROUPS + g) * SEQ * 64;
    const float* Vg = g_v + (size_t)(b * N_GROUPS + g) * SEQ * 64;

    for (int i = tid; i < 64 * 16; i += 256) {
        int r = i >> 4, c4 = (i & 15) << 2;
        *(float4*)&Qs[r][c4] = *(const float4*)(Qg + r * 64 + c4);
    }

    const int r0 = warp * 8;
    float m[8], l[8], o0[8], o1[8];
#pragma unroll
    for (int r = 0; r < 8; r++) { m[r] = -1e30f; l[r] = 0.f; o0[r] = 0.f; o1[r] = 0.f; }

    const float scale = 0.125f;

    for (int kt = 0; kt < SEQ / 32; kt++) {
        __syncthreads();
        for (int i = tid; i < 512; i += 256) {
            int r = i >> 4, c4 = (i & 15) << 2;
            float4 k4 = *(const float4*)(Kg + ((size_t)(kt * 32 + r)) * 64 + c4);
            Ks[r][c4] = k4.x; Ks[r][c4 + 1] = k4.y; Ks[r][c4 + 2] = k4.z; Ks[r][c4 + 3] = k4.w;
            *(float4*)&Vs[r][c4] = *(const float4*)(Vg + ((size_t)(kt * 32 + r)) * 64 + c4);
        }
        __syncthreads();

        float s[8];
#pragma unroll
        for (int r = 0; r < 8; r++) s[r] = 0.f;
#pragma unroll
        for (int d4 = 0; d4 < 64; d4 += 4) {
            float4 kv = *(const float4*)&Ks[lane][d4];
#pragma unroll
            for (int r = 0; r < 8; r++) {
                float4 qv = *(const float4*)&Qs[r0 + r][d4];
                s[r] += qv.x * kv.x + qv.y * kv.y + qv.z * kv.z + qv.w * kv.w;
            }
        }

        float p[8];
#pragma unroll
        for (int r = 0; r < 8; r++) {
            float sr = s[r] * scale;
            float mt = sr;
#pragma unroll
            for (int off = 16; off > 0; off >>= 1)
                mt = fmaxf(mt, __shfl_xor_sync(0xffffffffu, mt, off));
            float mn = fmaxf(m[r], mt);
            float pe = __expf(sr - mn);
            float alpha = __expf(m[r] - mn);
            float ps = pe;
#pragma unroll
            for (int off = 16; off > 0; off >>= 1)
                ps += __shfl_xor_sync(0xffffffffu, ps, off);
            l[r] = l[r] * alpha + ps;
            m[r] = mn;
            o0[r] *= alpha; o1[r] *= alpha;
            p[r] = pe;
        }

#pragma unroll
        for (int kk = 0; kk < 32; kk++) {
            float2 v2 = *(const float2*)&Vs[kk][lane * 2];
#pragma unroll
            for (int r = 0; r < 8; r++) {
                float pv = __shfl_sync(0xffffffffu, p[r], kk);
                o0[r] = fmaf(pv, v2.x, o0[r]);
                o1[r] = fmaf(pv, v2.y, o1[r]);
            }
        }
    }

#pragma unroll
    for (int r = 0; r < 8; r++) {
        int t = qt * 64 + r0 + r;
        float inv = 1.f / l[r];
        float rx = o0[r] * inv, ry = o1[r] * inv;
        __nv_bfloat16 hx = __float2bfloat16(rx);
        __nv_bfloat16 hy = __float2bfloat16(ry);
        __nv_bfloat16 lx = __float2bfloat16(rx - __bfloat162float(hx));
        __nv_bfloat16 ly = __float2bfloat16(ry - __bfloat162float(hy));
        size_t off = ((size_t)(b * SEQ + t)) * N_EMBD + h * 64 + lane * 2;
        uint32_t H = (uint32_t)__bfloat16_as_ushort(hx) | ((uint32_t)__bfloat16_as_ushort(hy) << 16);
        uint32_t L = (uint32_t)__bfloat16_as_ushort(lx) | ((uint32_t)__bfloat16_as_ushort(ly) << 16);
        *(uint32_t*)&g_ao_hi[off] = H;
        *(uint32_t*)&g_ao_lo[off] = L;
    }
}

// ---------------------------------------------------------------------------
extern "C" void kernel_launch(void* const* d_in, const int* in_sizes, int n_in,
                              void* d_out, int out_size)
{
    const float* x      = (const float*)d_in[0];
    const float* cosp   = (const float*)d_in[1];
    const float* sinp   = (const float*)d_in[2];
    const float* attn_w = (const float*)d_in[3];
    const float* proj_w = (const float*)d_in[4];
    float* out = (float*)d_out;

    float *qkv;
    cudaGetSymbolAddress((void**)&qkv, g_qkv);
    __nv_bfloat16 *xs_h, *xs_l, *aw_h, *aw_l, *pw_h, *pw_l, *ao_h, *ao_l;
    cudaGetSymbolAddress((void**)&xs_h, g_xs_hi);
    cudaGetSymbolAddress((void**)&xs_l, g_xs_lo);
    cudaGetSymbolAddress((void**)&aw_h, g_aw_hi);
    cudaGetSymbolAddress((void**)&aw_l, g_aw_lo);
    cudaGetSymbolAddress((void**)&pw_h, g_pw_hi);
    cudaGetSymbolAddress((void**)&pw_l, g_pw_lo);
    cudaGetSymbolAddress((void**)&ao_h, g_ao_hi);
    cudaGetSymbolAddress((void**)&ao_l, g_ao_lo);

    const int GSMEM = 2 * STAGE_B;  // 81920 bytes
    cudaFuncSetAttribute(gemm_mma, cudaFuncAttributeMaxDynamicSharedMemorySize, GSMEM);

    // 1) split inputs to bf16 hi/lo
    split_kernel<<<2048, 256>>>((const float4*)x, (uint2*)xs_h, (uint2*)xs_l,
                                (M_TOT * N_EMBD) / 4);
    split_kernel<<<2048, 256>>>((const float4*)attn_w, (uint2*)aw_h, (uint2*)aw_l,
                                (QKV_DIM * N_EMBD) / 4);
    split_kernel<<<2048, 256>>>((const float4*)proj_w, (uint2*)pw_h, (uint2*)pw_l,
                                (N_EMBD * N_EMBD) / 4);

    // 2) QKV projection (tensor cores via mma.sync)
    gemm_mma<<<dim3(QKV_DIM / 128, M_TOT / 128), 256, GSMEM>>>(
        xs_h, xs_l, aw_h, aw_l, qkv, M_TOT, QKV_DIM, N_EMBD);

    // 3) RoPE + head split
    rope_split<<<BATCH * SEQ, 256>>>(qkv, cosp, sinp);

    // 4) flash attention (emits split bf16 output)
    attn_kernel<<<dim3(SEQ / 64, BATCH * N_HEAD), 256>>>();

    // 5) output projection (tensor cores via mma.sync)
    gemm_mma<<<dim3(N_EMBD / 128, M_TOT / 128), 256, GSMEM>>>(
        ao_h, ao_l, pw_h, pw_l, out, M_TOT, N_EMBD, N_EMBD);
}

// round 6
// speedup vs baseline: 3.2078x; 2.3726x over previous
#include <cuda_runtime.h>
#include <cuda_bf16.h>
#include <cstdint>
#include <math.h>

#define N_EMBD   2048
#define N_HEAD   32
#define N_GROUPS 8
#define HEAD_DIM 64
#define Q_PER_KV 4
#define QKV_DIM  3072
#define BATCH    2
#define SEQ      2048
#define M_TOT    (BATCH*SEQ)   // 4096

// ---------------- scratch (device globals; no allocations allowed) ---------
__device__ float g_qkv[(size_t)M_TOT*QKV_DIM];

__device__ __align__(128) __nv_bfloat16 g_q_hi[(size_t)BATCH*N_HEAD*SEQ*HEAD_DIM];
__device__ __align__(128) __nv_bfloat16 g_q_lo[(size_t)BATCH*N_HEAD*SEQ*HEAD_DIM];
__device__ __align__(128) __nv_bfloat16 g_k_hi[(size_t)BATCH*N_GROUPS*SEQ*HEAD_DIM];
__device__ __align__(128) __nv_bfloat16 g_k_lo[(size_t)BATCH*N_GROUPS*SEQ*HEAD_DIM];
__device__ __align__(128) __nv_bfloat16 g_v_hi[(size_t)BATCH*N_GROUPS*SEQ*HEAD_DIM];
__device__ __align__(128) __nv_bfloat16 g_v_lo[(size_t)BATCH*N_GROUPS*SEQ*HEAD_DIM];

__device__ __align__(128) __nv_bfloat16 g_xs_hi[(size_t)M_TOT*N_EMBD];
__device__ __align__(128) __nv_bfloat16 g_xs_lo[(size_t)M_TOT*N_EMBD];
__device__ __align__(128) __nv_bfloat16 g_aw_hi[(size_t)QKV_DIM*N_EMBD];
__device__ __align__(128) __nv_bfloat16 g_aw_lo[(size_t)QKV_DIM*N_EMBD];
__device__ __align__(128) __nv_bfloat16 g_pw_hi[(size_t)N_EMBD*N_EMBD];
__device__ __align__(128) __nv_bfloat16 g_pw_lo[(size_t)N_EMBD*N_EMBD];
__device__ __align__(128) __nv_bfloat16 g_ao_hi[(size_t)M_TOT*N_EMBD];
__device__ __align__(128) __nv_bfloat16 g_ao_lo[(size_t)M_TOT*N_EMBD];

// ====================== helpers (sm_80-compatible PTX only) ================
static __device__ __forceinline__ uint32_t smem_u32(const void* p) {
    uint32_t a;
    asm("{ .reg .u64 t; cvta.to.shared.u64 t, %1; cvt.u32.u64 %0, t; }"
        : "=r"(a) : "l"(p));
    return a;
}

#define CP16(dst, src) \
    asm volatile("cp.async.cg.shared.global [%0], [%1], 16;" :: "r"(dst), "l"(src))
#define CPCOMMIT() asm volatile("cp.async.commit_group;")
#define CPWAIT1()  asm volatile("cp.async.wait_group 1;" ::: "memory")
#define CPWAIT0()  asm volatile("cp.async.wait_group 0;" ::: "memory")

#define LDSM4(r0, r1, r2, r3, addr) \
    asm volatile("ldmatrix.sync.aligned.m8n8.x4.shared.b16 {%0,%1,%2,%3}, [%4];" \
        : "=r"(r0), "=r"(r1), "=r"(r2), "=r"(r3) : "r"(addr))
#define LDSM4T(r0, r1, r2, r3, addr) \
    asm volatile("ldmatrix.sync.aligned.m8n8.x4.trans.shared.b16 {%0,%1,%2,%3}, [%4];" \
        : "=r"(r0), "=r"(r1), "=r"(r2), "=r"(r3) : "r"(addr))

#define MMA_BF16(c, a, b0, b1) \
    asm volatile("mma.sync.aligned.m16n8k16.row.col.f32.bf16.bf16.f32 " \
        "{%0,%1,%2,%3}, {%4,%5,%6,%7}, {%8,%9}, {%0,%1,%2,%3};" \
        : "+f"((c)[0]), "+f"((c)[1]), "+f"((c)[2]), "+f"((c)[3]) \
        : "r"((a)[0]), "r"((a)[1]), "r"((a)[2]), "r"((a)[3]), "r"(b0), "r"(b1))

static __device__ __forceinline__ uint32_t packbf2(float lo, float hi) {
    __nv_bfloat16 a = __float2bfloat16(lo), b = __float2bfloat16(hi);
    return (uint32_t)__bfloat16_as_ushort(a) | ((uint32_t)__bfloat16_as_ushort(b) << 16);
}
static __device__ __forceinline__ float blo(uint32_t r) { return __uint_as_float(r << 16); }
static __device__ __forceinline__ float bhi(uint32_t r) { return __uint_as_float(r & 0xffff0000u); }

static __device__ __forceinline__ void split2(float x, float y, uint32_t& H, uint32_t& L) {
    __nv_bfloat16 hx = __float2bfloat16(x), hy = __float2bfloat16(y);
    __nv_bfloat16 lx = __float2bfloat16(x - __bfloat162float(hx));
    __nv_bfloat16 ly = __float2bfloat16(y - __bfloat162float(hy));
    H = (uint32_t)__bfloat16_as_ushort(hx) | ((uint32_t)__bfloat16_as_ushort(hy) << 16);
    L = (uint32_t)__bfloat16_as_ushort(lx) | ((uint32_t)__bfloat16_as_ushort(ly) << 16);
}

// ================ fp32 -> bf16 hi/lo split (prepass) =======================
__global__ __launch_bounds__(256) void split_kernel(
    const float4* __restrict__ in, uint2* __restrict__ hi, uint2* __restrict__ lo, int n4)
{
    for (int i = blockIdx.x * blockDim.x + threadIdx.x; i < n4;
         i += gridDim.x * blockDim.x) {
        float4 v = in[i];
        uint2 H, L;
        split2(v.x, v.y, H.x, L.x);
        split2(v.z, v.w, H.y, L.y);
        hi[i] = H; lo[i] = L;
    }
}

// ============ mma.sync GEMM: C = A @ B^T (3-term bf16 split) ===============
#define ROWB 80
#define TILE_B (128*ROWB)
#define STAGE_B (4*TILE_B)

__device__ __forceinline__ void g_load_stage(
    const __nv_bfloat16* pAh, const __nv_bfloat16* pAl,
    const __nv_bfloat16* pBh, const __nv_bfloat16* pBl,
    int K, int k0, uint32_t base, int tid)
{
    const __nv_bfloat16* srcs[4] = { pAh, pAl, pBh, pBl };
#pragma unroll
    for (int t = 0; t < 4; t++) {
#pragma unroll
        for (int j = 0; j < 2; j++) {
            const int idx = (tid << 1) | j;
            const int row = idx >> 2, ch = idx & 3;
            const char* gsrc = (const char*)(srcs[t] + (size_t)row * K + k0) + ch * 16;
            uint32_t dst = base + t * TILE_B + row * ROWB + ch * 16;
            CP16(dst, gsrc);
        }
    }
    CPCOMMIT();
}

__global__ __launch_bounds__(256, 1) void gemm_mma(
    const __nv_bfloat16* __restrict__ Ah, const __nv_bfloat16* __restrict__ Al,
    const __nv_bfloat16* __restrict__ Bh, const __nv_bfloat16* __restrict__ Bl,
    float* __restrict__ C, int M, int N, int K)
{
    extern __shared__ char dynsmem[];
    const uint32_t tiles = smem_u32(dynsmem);

    const int tid = threadIdx.x, warp = tid >> 5, lane = tid & 31;
    const int bm = blockIdx.y, bn = blockIdx.x;
    const int wm = warp & 1, wn = warp >> 1;
    const int KC = K >> 5;

    const __nv_bfloat16* pAh = Ah + (size_t)(bm * 128) * K;
    const __nv_bfloat16* pAl = Al + (size_t)(bm * 128) * K;
    const __nv_bfloat16* pBh = Bh + (size_t)(bn * 128) * K;
    const __nv_bfloat16* pBl = Bl + (size_t)(bn * 128) * K;

    float acc[4][4][4];
#pragma unroll
    for (int i = 0; i < 4; i++)
#pragma unroll
        for (int j = 0; j < 4; j++)
#pragma unroll
            for (int q = 0; q < 4; q++) acc[i][j][q] = 0.f;

    g_load_stage(pAh, pAl, pBh, pBl, K, 0,  tiles,           tid);
    g_load_stage(pAh, pAl, pBh, pBl, K, 32, tiles + STAGE_B, tid);

    const int a_row = wm * 64 + (lane & 15);
    const int a_ko  = (lane >> 4) * 16;
    const int b_row = wn * 32 + ((lane >> 4) << 3) + (lane & 7);
    const int b_ko  = ((lane >> 3) & 1) * 16;

    for (int kc = 0; kc < KC; kc++) {
        const int s = kc & 1;
        if (kc + 1 < KC) { CPWAIT1(); } else { CPWAIT0(); }
        __syncthreads();

        const uint32_t sAh = tiles + s * STAGE_B;
        const uint32_t sAl = sAh + TILE_B;
        const uint32_t sBh = sAh + 2 * TILE_B;
        const uint32_t sBl = sAh + 3 * TILE_B;

#pragma unroll
        for (int ks = 0; ks < 2; ks++) {
            const int kb = ks * 32;
            uint32_t ah[4][4], al[4][4], bh[2][4], bl[2][4];
#pragma unroll
            for (int mf = 0; mf < 4; mf++) {
                uint32_t ad = sAh + (a_row + mf * 16) * ROWB + a_ko + kb;
                LDSM4(ah[mf][0], ah[mf][1], ah[mf][2], ah[mf][3], ad);
            }
#pragma unroll
            for (int np = 0; np < 2; np++) {
                uint32_t bd = sBh + (b_row + np * 16) * ROWB + b_ko + kb;
                LDSM4(bh[np][0], bh[np][1], bh[np][2], bh[np][3], bd);
            }
#pragma unroll
            for (int mf = 0; mf < 4; mf++)
#pragma unroll
                for (int nf = 0; nf < 4; nf++)
                    MMA_BF16(acc[mf][nf], ah[mf],
                             bh[nf >> 1][(nf & 1) * 2], bh[nf >> 1][(nf & 1) * 2 + 1]);
#pragma unroll
            for (int np = 0; np < 2; np++) {
                uint32_t bd = sBl + (b_row + np * 16) * ROWB + b_ko + kb;
                LDSM4(bl[np][0], bl[np][1], bl[np][2], bl[np][3], bd);
            }
#pragma unroll
            for (int mf = 0; mf < 4; mf++)
#pragma unroll
                for (int nf = 0; nf < 4; nf++)
                    MMA_BF16(acc[mf][nf], ah[mf],
                             bl[nf >> 1][(nf & 1) * 2], bl[nf >> 1][(nf & 1) * 2 + 1]);
#pragma unroll
            for (int mf = 0; mf < 4; mf++) {
                uint32_t ad = sAl + (a_row + mf * 16) * ROWB + a_ko + kb;
                LDSM4(al[mf][0], al[mf][1], al[mf][2], al[mf][3], ad);
            }
#pragma unroll
            for (int mf = 0; mf < 4; mf++)
#pragma unroll
                for (int nf = 0; nf < 4; nf++)
                    MMA_BF16(acc[mf][nf], al[mf],
                             bh[nf >> 1][(nf & 1) * 2], bh[nf >> 1][(nf & 1) * 2 + 1]);
        }
        __syncthreads();
        if (kc + 2 < KC)
            g_load_stage(pAh, pAl, pBh, pBl, K, (kc + 2) << 5, tiles + s * STAGE_B, tid);
    }

    const int g = lane >> 2, tig = lane & 3;
#pragma unroll
    for (int mf = 0; mf < 4; mf++) {
#pragma unroll
        for (int nf = 0; nf < 4; nf++) {
            const int row = bm * 128 + wm * 64 + mf * 16 + g;
            const int col = bn * 128 + wn * 32 + nf * 8 + tig * 2;
            float2 r0; r0.x = acc[mf][nf][0]; r0.y = acc[mf][nf][1];
            float2 r1; r1.x = acc[mf][nf][2]; r1.y = acc[mf][nf][3];
            *(float2*)&C[(size_t)row * N + col]       = r0;
            *(float2*)&C[(size_t)(row + 8) * N + col] = r1;
        }
    }
}

// ------- RoPE + split qkv -> bf16 hi/lo q[B,H,T,D], k/v[B,G,T,D] ----------
__global__ __launch_bounds__(256) void rope_split(
    const float* __restrict__ qkv,
    const float* __restrict__ cosT, const float* __restrict__ sinT)
{
    const int bt = blockIdx.x;
    const int b = bt / SEQ, t = bt % SEQ;
    const float* row = qkv + (size_t)bt * QKV_DIM;

    __shared__ float cs[32], sn[32];
    if (threadIdx.x < 32) {
        cs[threadIdx.x] = cosT[t * 32 + threadIdx.x];
        sn[threadIdx.x] = sinT[t * 32 + threadIdx.x];
    }
    __syncthreads();

    for (int it = threadIdx.x; it < 1024; it += 256) {
        int h = it >> 5, j = it & 31;
        int kvg = h >> 2, slot = h & 3;
        const float* src = row + (kvg * 6 + slot) * 64;
        float x1 = src[j], x2 = src[j + 32];
        float c = cs[j], s = sn[j];
        float r1 = x1 * c - x2 * s, r2 = x2 * c + x1 * s;
        size_t base = ((size_t)(b * N_HEAD + h) * SEQ + t) * 64;
        __nv_bfloat16 h1 = __float2bfloat16(r1), h2 = __float2bfloat16(r2);
        g_q_hi[base + j]      = h1;
        g_q_lo[base + j]      = __float2bfloat16(r1 - __bfloat162float(h1));
        g_q_hi[base + j + 32] = h2;
        g_q_lo[base + j + 32] = __float2bfloat16(r2 - __bfloat162float(h2));
    }
    {
        int it = threadIdx.x;
        int kvg = it >> 5, j = it & 31;
        const float* src = row + (kvg * 6 + 4) * 64;
        float x1 = src[j], x2 = src[j + 32];
        float c = cs[j], s = sn[j];
        float r1 = x1 * c - x2 * s, r2 = x2 * c + x1 * s;
        size_t base = ((size_t)(b * N_GROUPS + kvg) * SEQ + t) * 64;
        __nv_bfloat16 h1 = __float2bfloat16(r1), h2 = __float2bfloat16(r2);
        g_k_hi[base + j]      = h1;
        g_k_lo[base + j]      = __float2bfloat16(r1 - __bfloat162float(h1));
        g_k_hi[base + j + 32] = h2;
        g_k_lo[base + j + 32] = __float2bfloat16(r2 - __bfloat162float(h2));
    }
    for (int it = threadIdx.x; it < 512; it += 256) {
        int kvg = it >> 6, d = it & 63;
        float v = row[(kvg * 6 + 5) * 64 + d];
        size_t base = ((size_t)(b * N_GROUPS + kvg) * SEQ + t) * 64 + d;
        __nv_bfloat16 hv = __float2bfloat16(v);
        g_v_hi[base] = hv;
        g_v_lo[base] = __float2bfloat16(v - __bfloat162float(hv));
    }
}

// =============== tensor-core flash attention (3-term bf16) =================
#define ATT_STRIDE 144
#define ATT_QBYTES (128*ATT_STRIDE)
#define ATT_TILE   (64*ATT_STRIDE)
#define ATT_STAGE  (4*ATT_TILE)
#define ATT_SMEM   (2*ATT_QBYTES + 2*ATT_STAGE)   // 110592

__global__ __launch_bounds__(256, 1) void attn_tc()
{
    extern __shared__ char asmem[];
    const uint32_t sQh = smem_u32(asmem);
    const uint32_t sQl = sQh + ATT_QBYTES;
    const uint32_t sKV = sQh + 2 * ATT_QBYTES;

    const int tid = threadIdx.x, warp = tid >> 5, lane = tid & 31;
    const int lg = lane >> 2, tg = lane & 3;
    const int qt = blockIdx.x, bhid = blockIdx.y;
    const int b = bhid >> 5, h = bhid & 31, kvg = h >> 2;

    const __nv_bfloat16* Qhp = g_q_hi + ((size_t)(b * N_HEAD + h) * SEQ + qt * 128) * 64;
    const __nv_bfloat16* Qlp = g_q_lo + ((size_t)(b * N_HEAD + h) * SEQ + qt * 128) * 64;
    const __nv_bfloat16* Khp = g_k_hi + (size_t)(b * N_GROUPS + kvg) * SEQ * 64;
    const __nv_bfloat16* Klp = g_k_lo + (size_t)(b * N_GROUPS + kvg) * SEQ * 64;
    const __nv_bfloat16* Vhp = g_v_hi + (size_t)(b * N_GROUPS + kvg) * SEQ * 64;
    const __nv_bfloat16* Vlp = g_v_lo + (size_t)(b * N_GROUPS + kvg) * SEQ * 64;

    auto load_kv = [&](int kt, int st) {
        uint32_t base = sKV + st * ATT_STAGE;
        const __nv_bfloat16* s0 = Khp + (size_t)kt * 64 * 64;
        const __nv_bfloat16* s1 = Klp + (size_t)kt * 64 * 64;
        const __nv_bfloat16* s2 = Vhp + (size_t)kt * 64 * 64;
        const __nv_bfloat16* s3 = Vlp + (size_t)kt * 64 * 64;
        for (int i = tid; i < 512; i += 256) {
            int r = i >> 3, c = (i & 7) * 16;
            CP16(base                + r * ATT_STRIDE + c, (const char*)(s0 + r * 64) + c);
            CP16(base +     ATT_TILE + r * ATT_STRIDE + c, (const char*)(s1 + r * 64) + c);
            CP16(base + 2 * ATT_TILE + r * ATT_STRIDE + c, (const char*)(s2 + r * 64) + c);
            CP16(base + 3 * ATT_TILE + r * ATT_STRIDE + c, (const char*)(s3 + r * 64) + c);
        }
        CPCOMMIT();
    };

    // prologue: Q + KV0 in one group, KV1 in the next
    for (int i = tid; i < 1024; i += 256) {
        int r = i >> 3, c = (i & 7) * 16;
        CP16(sQh + r * ATT_STRIDE + c, (const char*)(Qhp + r * 64) + c);
        CP16(sQl + r * ATT_STRIDE + c, (const char*)(Qlp + r * 64) + c);
    }
    load_kv(0, 0);   // commits {Q, KV0}
    load_kv(1, 1);

    float o[8][4];
#pragma unroll
    for (int nf = 0; nf < 8; nf++)
#pragma unroll
        for (int i = 0; i < 4; i++) o[nf][i] = 0.f;
    float m0 = -1e30f, m1 = -1e30f, l0 = 0.f, l1 = 0.f;
    uint32_t qh[4][4], ql[4][4];

    const int a_row = warp * 16 + (lane & 15);
    const int a_ko  = (lane >> 4) * 16;
    const int b_row = ((lane >> 4) << 3) + (lane & 7);
    const int b_ko  = ((lane >> 3) & 1) * 16;
    const int vq    = lane >> 3;
    const int v_row = (vq & 1) * 8 + (lane & 7);
    const int v_co  = (vq >> 1) * 16;

    for (int kt = 0; kt < SEQ / 64; kt++) {
        const int st = kt & 1;
        if (kt + 1 < SEQ / 64) { CPWAIT1(); } else { CPWAIT0(); }
        __syncthreads();
        const uint32_t sK  = sKV + st * ATT_STAGE;
        const uint32_t sKl = sK + ATT_TILE;
        const uint32_t sV  = sK + 2 * ATT_TILE;
        const uint32_t sVl = sK + 3 * ATT_TILE;

        if (kt == 0) {
#pragma unroll
            for (int ks = 0; ks < 4; ks++) {
                LDSM4(qh[ks][0], qh[ks][1], qh[ks][2], qh[ks][3],
                      sQh + a_row * ATT_STRIDE + a_ko + ks * 32);
                LDSM4(ql[ks][0], ql[ks][1], ql[ks][2], ql[ks][3],
                      sQl + a_row * ATT_STRIDE + a_ko + ks * 32);
            }
        }

        // ---- S = Q K^T (3-term) ----
        float s[8][4];
#pragma unroll
        for (int nf = 0; nf < 8; nf++)
#pragma unroll
            for (int i = 0; i < 4; i++) s[nf][i] = 0.f;

#pragma unroll
        for (int ks = 0; ks < 4; ks++) {
            const int kb = ks * 32;
            uint32_t kh[4][4], kl[4][4];
#pragma unroll
            for (int np = 0; np < 4; np++)
                LDSM4(kh[np][0], kh[np][1], kh[np][2], kh[np][3],
                      sK + (np * 16 + b_row) * ATT_STRIDE + b_ko + kb);
#pragma unroll
            for (int nf = 0; nf < 8; nf++)
                MMA_BF16(s[nf], qh[ks], kh[nf >> 1][(nf & 1) * 2], kh[nf >> 1][(nf & 1) * 2 + 1]);
#pragma unroll
            for (int np = 0; np < 4; np++)
                LDSM4(kl[np][0], kl[np][1], kl[np][2], kl[np][3],
                      sKl + (np * 16 + b_row) * ATT_STRIDE + b_ko + kb);
#pragma unroll
            for (int nf = 0; nf < 8; nf++)
                MMA_BF16(s[nf], qh[ks], kl[nf >> 1][(nf & 1) * 2], kl[nf >> 1][(nf & 1) * 2 + 1]);
#pragma unroll
            for (int nf = 0; nf < 8; nf++)
                MMA_BF16(s[nf], ql[ks], kh[nf >> 1][(nf & 1) * 2], kh[nf >> 1][(nf & 1) * 2 + 1]);
        }

        // ---- online softmax ----
#pragma unroll
        for (int nf = 0; nf < 8; nf++)
#pragma unroll
            for (int i = 0; i < 4; i++) s[nf][i] *= 0.125f;

        float mt0 = -1e30f, mt1 = -1e30f;
#pragma unroll
        for (int nf = 0; nf < 8; nf++) {
            mt0 = fmaxf(mt0, fmaxf(s[nf][0], s[nf][1]));
            mt1 = fmaxf(mt1, fmaxf(s[nf][2], s[nf][3]));
        }
        mt0 = fmaxf(mt0, __shfl_xor_sync(0xffffffffu, mt0, 1));
        mt0 = fmaxf(mt0, __shfl_xor_sync(0xffffffffu, mt0, 2));
        mt1 = fmaxf(mt1, __shfl_xor_sync(0xffffffffu, mt1, 1));
        mt1 = fmaxf(mt1, __shfl_xor_sync(0xffffffffu, mt1, 2));
        float mn0 = fmaxf(m0, mt0), mn1 = fmaxf(m1, mt1);
        float al0 = __expf(m0 - mn0), al1 = __expf(m1 - mn1);
        m0 = mn0; m1 = mn1;
        float sum0 = 0.f, sum1 = 0.f;
#pragma unroll
        for (int nf = 0; nf < 8; nf++) {
            s[nf][0] = __expf(s[nf][0] - mn0);
            s[nf][1] = __expf(s[nf][1] - mn0);
            s[nf][2] = __expf(s[nf][2] - mn1);
            s[nf][3] = __expf(s[nf][3] - mn1);
            sum0 += s[nf][0] + s[nf][1];
            sum1 += s[nf][2] + s[nf][3];
        }
        sum0 += __shfl_xor_sync(0xffffffffu, sum0, 1);
        sum0 += __shfl_xor_sync(0xffffffffu, sum0, 2);
        sum1 += __shfl_xor_sync(0xffffffffu, sum1, 1);
        sum1 += __shfl_xor_sync(0xffffffffu, sum1, 2);
        l0 = l0 * al0 + sum0;
        l1 = l1 * al1 + sum1;
#pragma unroll
        for (int nf = 0; nf < 8; nf++) {
            o[nf][0] *= al0; o[nf][1] *= al0; o[nf][2] *= al1; o[nf][3] *= al1;
        }

        // ---- O += P V (3-term), P from registers ----
#pragma unroll
        for (int j = 0; j < 4; j++) {
            const float* pa = s[2 * j];
            const float* pb = s[2 * j + 1];
            uint32_t ah[4], al_[4];
            ah[0] = packbf2(pa[0], pa[1]);
            ah[1] = packbf2(pa[2], pa[3]);
            ah[2] = packbf2(pb[0], pb[1]);
            ah[3] = packbf2(pb[2], pb[3]);
            al_[0] = packbf2(pa[0] - blo(ah[0]), pa[1] - bhi(ah[0]));
            al_[1] = packbf2(pa[2] - blo(ah[1]), pa[3] - bhi(ah[1]));
            al_[2] = packbf2(pb[0] - blo(ah[2]), pb[1] - bhi(ah[2]));
            al_[3] = packbf2(pb[2] - blo(ah[3]), pb[3] - bhi(ah[3]));

            const int k0 = j * 16;
            uint32_t vh[4][4], vl[4][4];
#pragma unroll
            for (int dd = 0; dd < 4; dd++)
                LDSM4T(vh[dd][0], vh[dd][1], vh[dd][2], vh[dd][3],
                       sV + (k0 + v_row) * ATT_STRIDE + dd * 32 + v_co);
#pragma unroll
            for (int dd = 0; dd < 4; dd++)
                LDSM4T(vl[dd][0], vl[dd][1], vl[dd][2], vl[dd][3],
                       sVl + (k0 + v_row) * ATT_STRIDE + dd * 32 + v_co);
#pragma unroll
            for (int nf = 0; nf < 8; nf++)
                MMA_BF16(o[nf], ah,  vh[nf >> 1][(nf & 1) * 2], vh[nf >> 1][(nf & 1) * 2 + 1]);
#pragma unroll
            for (int nf = 0; nf < 8; nf++)
                MMA_BF16(o[nf], al_, vh[nf >> 1][(nf & 1) * 2], vh[nf >> 1][(nf & 1) * 2 + 1]);
#pragma unroll
            for (int nf = 0; nf < 8; nf++)
                MMA_BF16(o[nf], ah,  vl[nf >> 1][(nf & 1) * 2], vl[nf >> 1][(nf & 1) * 2 + 1]);
        }

        __syncthreads();
        if (kt + 2 < SEQ / 64) load_kv(kt + 2, st);
    }

    // ---- epilogue: O/l, split to bf16 hi/lo, store ----
    const float inv0 = 1.f / l0, inv1 = 1.f / l1;
    const int t0 = qt * 128 + warp * 16 + lg;
#pragma unroll
    for (int nf = 0; nf < 8; nf++) {
        const int d = nf * 8 + tg * 2;
        size_t off0 = ((size_t)(b * SEQ + t0)) * N_EMBD + h * 64 + d;
        size_t off1 = off0 + (size_t)8 * N_EMBD;
        uint32_t H, L;
        split2(o[nf][0] * inv0, o[nf][1] * inv0, H, L);
        *(uint32_t*)&g_ao_hi[off0] = H;
        *(uint32_t*)&g_ao_lo[off0] = L;
        split2(o[nf][2] * inv1, o[nf][3] * inv1, H, L);
        *(uint32_t*)&g_ao_hi[off1] = H;
        *(uint32_t*)&g_ao_lo[off1] = L;
    }
}

// ---------------------------------------------------------------------------
extern "C" void kernel_launch(void* const* d_in, const int* in_sizes, int n_in,
                              void* d_out, int out_size)
{
    const float* x      = (const float*)d_in[0];
    const float* cosp   = (const float*)d_in[1];
    const float* sinp   = (const float*)d_in[2];
    const float* attn_w = (const float*)d_in[3];
    const float* proj_w = (const float*)d_in[4];
    float* out = (float*)d_out;

    float *qkv;
    cudaGetSymbolAddress((void**)&qkv, g_qkv);
    __nv_bfloat16 *xs_h, *xs_l, *aw_h, *aw_l, *pw_h, *pw_l, *ao_h, *ao_l;
    cudaGetSymbolAddress((void**)&xs_h, g_xs_hi);
    cudaGetSymbolAddress((void**)&xs_l, g_xs_lo);
    cudaGetSymbolAddress((void**)&aw_h, g_aw_hi);
    cudaGetSymbolAddress((void**)&aw_l, g_aw_lo);
    cudaGetSymbolAddress((void**)&pw_h, g_pw_hi);
    cudaGetSymbolAddress((void**)&pw_l, g_pw_lo);
    cudaGetSymbolAddress((void**)&ao_h, g_ao_hi);
    cudaGetSymbolAddress((void**)&ao_l, g_ao_lo);

    const int GSMEM = 2 * STAGE_B;
    cudaFuncSetAttribute(gemm_mma, cudaFuncAttributeMaxDynamicSharedMemorySize, GSMEM);
    cudaFuncSetAttribute(attn_tc, cudaFuncAttributeMaxDynamicSharedMemorySize, ATT_SMEM);

    // 1) split inputs to bf16 hi/lo
    split_kernel<<<2048, 256>>>((const float4*)x, (uint2*)xs_h, (uint2*)xs_l,
                                (M_TOT * N_EMBD) / 4);
    split_kernel<<<2048, 256>>>((const float4*)attn_w, (uint2*)aw_h, (uint2*)aw_l,
                                (QKV_DIM * N_EMBD) / 4);
    split_kernel<<<2048, 256>>>((const float4*)proj_w, (uint2*)pw_h, (uint2*)pw_l,
                                (N_EMBD * N_EMBD) / 4);

    // 2) QKV projection (tensor cores)
    gemm_mma<<<dim3(QKV_DIM / 128, M_TOT / 128), 256, GSMEM>>>(
        xs_h, xs_l, aw_h, aw_l, qkv, M_TOT, QKV_DIM, N_EMBD);

    // 3) RoPE + head split (emits bf16 hi/lo q/k/v)
    rope_split<<<BATCH * SEQ, 256>>>(qkv, cosp, sinp);

    // 4) tensor-core flash attention (emits split bf16 output)
    attn_tc<<<dim3(SEQ / 128, BATCH * N_HEAD), 256, ATT_SMEM>>>();

    // 5) output projection (tensor cores)
    gemm_mma<<<dim3(N_EMBD / 128, M_TOT / 128), 256, GSMEM>>>(
        ao_h, ao_l, pw_h, pw_l, out, M_TOT, N_EMBD, N_EMBD);
}